// round 1
// baseline (speedup 1.0000x reference)
#include <cuda_runtime.h>
#include <math.h>

#define B_    8
#define HW_   4096
#define K_    256
#define HID_  1024
#define AUX_  512
#define QK_   512
#define NH_   8
#define HD_   128
#define QH_   64
#define SCALE_ 0.08838834764831845f   // 1/sqrt(128)

// ---------------- scratch (static device global; no runtime allocs) ----------
// layout (floats):
//  q1   @ 0          : 2048*512   = 1,048,576
//  k1   @ 1,048,576  : 32768*512  = 16,777,216
//  v1   @ 17,825,792 : 32768*1024 = 33,554,432   (reused later as out2p)
//  q2   @ 51,380,224 : 32768*512  = 16,777,216
//  k2   @ 68,157,440 : 2048*512   = 1,048,576
//  v2   @ 69,206,016 : 2048*1024  = 2,097,152
//  ao1  @ 71,303,168 : 2048*1024  = 2,097,152
//  out1 @ 73,400,320 : 2048*512   = 1,048,576
//  ao2  @ 74,448,896 : 32768*1024 = 33,554,432
__device__ float g_scratch[108003328];

// ---------------- generic batched SGEMM -------------------------------------
// C[M,N] = alpha * A[M,Kd] * op(B) + bias,  op(B)=B^T (TRANSB: B is [N,Kd])
// or op(B)=B ([Kd,N]).  Batched over blockIdx.z with (b,h) strides.
// Tiles: 128x128x8, 256 threads, 8x8 per thread. All dims are multiples of
// the tile sizes for this problem, so no bounds checks.
template<bool TRANSB>
__global__ __launch_bounds__(256, 2) void gemm_kernel(
    const float* __restrict__ A, const float* __restrict__ Bm,
    const float* __restrict__ bias, float* __restrict__ C,
    int M, int N, int Kd, int lda, int ldb, int ldc,
    long long sAb, long long sAh, long long sBb, long long sBh,
    long long sCb, long long sCh, int nh, float alpha)
{
    __shared__ float As[8][128];
    __shared__ float Bs[8][128];

    const int z  = blockIdx.z;
    const int bb = z / nh, hh = z - bb * nh;
    A  += bb * sAb + hh * sAh;
    Bm += bb * sBb + hh * sBh;
    C  += bb * sCb + hh * sCh;

    const int m0 = blockIdx.y * 128;
    const int n0 = blockIdx.x * 128;
    const int t  = threadIdx.x;
    const int tx = t & 15, ty = t >> 4;

    float acc[8][8];
#pragma unroll
    for (int i = 0; i < 8; i++)
#pragma unroll
        for (int j = 0; j < 8; j++) acc[i][j] = 0.f;

    const int lrow = t >> 1;           // 0..127
    const int lkq  = (t & 1) * 4;      // 0 or 4
    const int bkr  = t >> 5;           // 0..7   (NN)
    const int bnc  = (t & 31) * 4;     // 0..124 (NN)

    const float* Aload = A + (size_t)(m0 + lrow) * lda + lkq;
    const float* Bload = TRANSB ? (Bm + (size_t)(n0 + lrow) * ldb + lkq)
                                : (Bm + (size_t)bkr * ldb + n0 + bnc);

    for (int k0 = 0; k0 < Kd; k0 += 8) {
        float4 a4 = *reinterpret_cast<const float4*>(Aload + k0);
        As[lkq + 0][lrow] = a4.x; As[lkq + 1][lrow] = a4.y;
        As[lkq + 2][lrow] = a4.z; As[lkq + 3][lrow] = a4.w;
        if (TRANSB) {
            float4 b4 = *reinterpret_cast<const float4*>(Bload + k0);
            Bs[lkq + 0][lrow] = b4.x; Bs[lkq + 1][lrow] = b4.y;
            Bs[lkq + 2][lrow] = b4.z; Bs[lkq + 3][lrow] = b4.w;
        } else {
            float4 b4 = *reinterpret_cast<const float4*>(Bload + (size_t)k0 * ldb);
            *reinterpret_cast<float4*>(&Bs[bkr][bnc]) = b4;
        }
        __syncthreads();
#pragma unroll
        for (int kk = 0; kk < 8; kk++) {
            float a[8], b[8];
            *reinterpret_cast<float4*>(a)     = *reinterpret_cast<const float4*>(&As[kk][ty * 8]);
            *reinterpret_cast<float4*>(a + 4) = *reinterpret_cast<const float4*>(&As[kk][ty * 8 + 4]);
            *reinterpret_cast<float4*>(b)     = *reinterpret_cast<const float4*>(&Bs[kk][tx * 8]);
            *reinterpret_cast<float4*>(b + 4) = *reinterpret_cast<const float4*>(&Bs[kk][tx * 8 + 4]);
#pragma unroll
            for (int i = 0; i < 8; i++)
#pragma unroll
                for (int j = 0; j < 8; j++)
                    acc[i][j] = fmaf(a[i], b[j], acc[i][j]);
        }
        __syncthreads();
    }

#pragma unroll
    for (int i = 0; i < 8; i++) {
        const int row = m0 + ty * 8 + i;
        float* Cp = C + (size_t)row * ldc + n0 + tx * 8;
#pragma unroll
        for (int j = 0; j < 8; j += 4) {
            float4 v;
            v.x = acc[i][j + 0] * alpha;
            v.y = acc[i][j + 1] * alpha;
            v.z = acc[i][j + 2] * alpha;
            v.w = acc[i][j + 3] * alpha;
            if (bias) {
                const float* bp = bias + n0 + tx * 8 + j;
                v.x += bp[0]; v.y += bp[1]; v.z += bp[2]; v.w += bp[3];
            }
            *reinterpret_cast<float4*>(Cp + j) = v;
        }
    }
}

// ---------------- softmax, L = 4096, one block per row ----------------------
__global__ __launch_bounds__(256) void softmax4096_kernel(float* __restrict__ X)
{
    float* x = X + (size_t)blockIdx.x * 4096;
    const int t = threadIdx.x;
    float v[16];
    float m = -1e30f;
#pragma unroll
    for (int i = 0; i < 16; i++) { v[i] = x[t + i * 256]; m = fmaxf(m, v[i]); }
    __shared__ float red[8];
    const int lane = t & 31, w = t >> 5;
#pragma unroll
    for (int o = 16; o > 0; o >>= 1) m = fmaxf(m, __shfl_xor_sync(0xffffffffu, m, o));
    if (lane == 0) red[w] = m;
    __syncthreads();
    float bm = red[0];
#pragma unroll
    for (int i = 1; i < 8; i++) bm = fmaxf(bm, red[i]);
    float s = 0.f;
#pragma unroll
    for (int i = 0; i < 16; i++) { v[i] = __expf(v[i] - bm); s += v[i]; }
#pragma unroll
    for (int o = 16; o > 0; o >>= 1) s += __shfl_xor_sync(0xffffffffu, s, o);
    __syncthreads();
    if (lane == 0) red[w] = s;
    __syncthreads();
    float bs = 0.f;
#pragma unroll
    for (int i = 0; i < 8; i++) bs += red[i];
    const float inv = 1.0f / bs;
#pragma unroll
    for (int i = 0; i < 16; i++) x[t + i * 256] = v[i] * inv;
}

// ---------------- softmax, L = 256, one warp per row ------------------------
__global__ __launch_bounds__(256) void softmax256_kernel(float* __restrict__ X)
{
    const int lane = threadIdx.x & 31;
    const int w    = threadIdx.x >> 5;
    float* x = X + ((size_t)blockIdx.x * 8 + w) * 256;
    float v[8];
    float m = -1e30f;
#pragma unroll
    for (int i = 0; i < 8; i++) { v[i] = x[lane + i * 32]; m = fmaxf(m, v[i]); }
#pragma unroll
    for (int o = 16; o > 0; o >>= 1) m = fmaxf(m, __shfl_xor_sync(0xffffffffu, m, o));
    float s = 0.f;
#pragma unroll
    for (int i = 0; i < 8; i++) { v[i] = __expf(v[i] - m); s += v[i]; }
#pragma unroll
    for (int o = 16; o > 0; o >>= 1) s += __shfl_xor_sync(0xffffffffu, s, o);
    const float inv = 1.0f / s;
#pragma unroll
    for (int i = 0; i < 8; i++) x[lane + i * 32] = v[i] * inv;
}

// ---------------- residual add + LayerNorm ----------------------------------
template<int VPT>
__global__ __launch_bounds__(256) void add_ln_kernel(
    const float* __restrict__ R, const float* __restrict__ X,
    const float* __restrict__ g, const float* __restrict__ bta,
    float* __restrict__ Y, int D)
{
    const size_t row = blockIdx.x;
    const float* r = R + row * D;
    const float* x = X + row * D;
    float* y = Y + row * D;
    const int t = threadIdx.x;
    float v[VPT];
    float s = 0.f, sq = 0.f;
#pragma unroll
    for (int i = 0; i < VPT; i++) {
        const int c = t + i * 256;
        v[i] = r[c] + x[c];
        s += v[i]; sq += v[i] * v[i];
    }
    const int lane = t & 31, w = t >> 5;
#pragma unroll
    for (int o = 16; o > 0; o >>= 1) {
        s  += __shfl_xor_sync(0xffffffffu, s, o);
        sq += __shfl_xor_sync(0xffffffffu, sq, o);
    }
    __shared__ float rs[8], rq[8];
    if (lane == 0) { rs[w] = s; rq[w] = sq; }
    __syncthreads();
    s = 0.f; sq = 0.f;
#pragma unroll
    for (int i = 0; i < 8; i++) { s += rs[i]; sq += rq[i]; }
    const float mean = s / D;
    const float var  = sq / D - mean * mean;
    const float inv  = rsqrtf(var + 1e-5f);
#pragma unroll
    for (int i = 0; i < VPT; i++) {
        const int c = t + i * 256;
        y[c] = (v[i] - mean) * inv * g[c] + bta[c];
    }
}

// ---------------- launch ------------------------------------------------------
extern "C" void kernel_launch(void* const* d_in, const int* in_sizes, int n_in,
                              void* d_out, int out_size)
{
    const float* hidden = (const float*)d_in[0];
    const float* aux    = (const float*)d_in[1];
    const float* wq1 = (const float*)d_in[2];  const float* bq1 = (const float*)d_in[3];
    const float* wk1 = (const float*)d_in[4];  const float* bk1 = (const float*)d_in[5];
    const float* wv1 = (const float*)d_in[6];  const float* bv1 = (const float*)d_in[7];
    const float* wo1 = (const float*)d_in[8];  const float* bo1 = (const float*)d_in[9];
    const float* wq2 = (const float*)d_in[10]; const float* bq2 = (const float*)d_in[11];
    const float* wk2 = (const float*)d_in[12]; const float* bk2 = (const float*)d_in[13];
    const float* wv2 = (const float*)d_in[14]; const float* bv2 = (const float*)d_in[15];
    const float* wo2 = (const float*)d_in[16]; const float* bo2 = (const float*)d_in[17];
    const float* g_aux = (const float*)d_in[18]; const float* b_aux = (const float*)d_in[19];
    const float* g_h   = (const float*)d_in[20]; const float* b_h   = (const float*)d_in[21];

    float* scratch = nullptr;
    cudaGetSymbolAddress((void**)&scratch, g_scratch);
    float* q1    = scratch + 0;
    float* k1    = scratch + 1048576;
    float* v1    = scratch + 17825792;
    float* q2    = scratch + 51380224;
    float* k2    = scratch + 68157440;
    float* v2    = scratch + 69206016;
    float* ao1   = scratch + 71303168;
    float* out1  = scratch + 73400320;
    float* ao2   = scratch + 74448896;
    float* out2p = v1;  // v1 dead after attn1@v1; reuse for out2 projection

    float* out     = (float*)d_out;
    float* aux_out = out + (size_t)B_ * HW_ * HID_;
    float* attn2   = aux_out + (size_t)B_ * K_ * AUX_;
    float* attn1   = attn2 + (size_t)B_ * NH_ * HW_ * K_;

    // --- projections from inputs ---
    // q1 = aux @ wq1^T + bq1       (2048 x 512 x 512)
    gemm_kernel<true><<<dim3(4, 16, 1), 256>>>(aux, wq1, bq1, q1,
        2048, 512, 512, 512, 512, 512, 0, 0, 0, 0, 0, 0, 1, 1.f);
    // k1 = hidden @ wk1^T + bk1    (32768 x 512 x 1024)
    gemm_kernel<true><<<dim3(4, 256, 1), 256>>>(hidden, wk1, bk1, k1,
        32768, 512, 1024, 1024, 1024, 512, 0, 0, 0, 0, 0, 0, 1, 1.f);
    // v1 = hidden @ wv1^T + bv1    (32768 x 1024 x 1024)
    gemm_kernel<true><<<dim3(8, 256, 1), 256>>>(hidden, wv1, bv1, v1,
        32768, 1024, 1024, 1024, 1024, 1024, 0, 0, 0, 0, 0, 0, 1, 1.f);
    // q2 = hidden @ wq2^T + bq2    (32768 x 512 x 1024)
    gemm_kernel<true><<<dim3(4, 256, 1), 256>>>(hidden, wq2, bq2, q2,
        32768, 512, 1024, 1024, 1024, 512, 0, 0, 0, 0, 0, 0, 1, 1.f);

    // --- pack attention: scores (b,h): 256 x 4096, headdim 64 ---
    gemm_kernel<true><<<dim3(32, 2, 64), 256>>>(q1, k1, nullptr, attn1,
        256, 4096, 64, 512, 512, 4096,
        (long long)K_ * QK_, 64,
        (long long)HW_ * QK_, 64,
        (long long)NH_ * K_ * HW_, (long long)K_ * HW_, NH_, SCALE_);
    softmax4096_kernel<<<16384, 256>>>(attn1);
    // ao1 = attn1 @ v1 (per head): 256 x 128 x 4096
    gemm_kernel<false><<<dim3(1, 2, 64), 256>>>(attn1, v1, nullptr, ao1,
        256, 128, 4096, 4096, 1024, 1024,
        (long long)NH_ * K_ * HW_, (long long)K_ * HW_,
        (long long)HW_ * HID_, HD_,
        (long long)K_ * HID_, HD_, NH_, 1.f);
    // out1 = ao1 @ wo1^T + bo1     (2048 x 512 x 1024)
    gemm_kernel<true><<<dim3(4, 16, 1), 256>>>(ao1, wo1, bo1, out1,
        2048, 512, 1024, 1024, 1024, 512, 0, 0, 0, 0, 0, 0, 1, 1.f);
    // aux_out = LN(aux + out1)
    add_ln_kernel<2><<<2048, 256>>>(aux, out1, g_aux, b_aux, aux_out, 512);

    // --- unpack attention: k2/v2 from pre-norm out1 ---
    gemm_kernel<true><<<dim3(4, 16, 1), 256>>>(out1, wk2, bk2, k2,
        2048, 512, 512, 512, 512, 512, 0, 0, 0, 0, 0, 0, 1, 1.f);
    gemm_kernel<true><<<dim3(8, 16, 1), 256>>>(out1, wv2, bv2, v2,
        2048, 1024, 512, 512, 512, 1024, 0, 0, 0, 0, 0, 0, 1, 1.f);
    // scores (b,h): 4096 x 256, headdim 64
    gemm_kernel<true><<<dim3(2, 32, 64), 256>>>(q2, k2, nullptr, attn2,
        4096, 256, 64, 512, 512, 256,
        (long long)HW_ * QK_, 64,
        (long long)K_ * QK_, 64,
        (long long)NH_ * HW_ * K_, (long long)HW_ * K_, NH_, SCALE_);
    softmax256_kernel<<<32768, 256>>>(attn2);
    // ao2 = attn2 @ v2 (per head): 4096 x 128 x 256
    gemm_kernel<false><<<dim3(1, 32, 64), 256>>>(attn2, v2, nullptr, ao2,
        4096, 128, 256, 256, 1024, 1024,
        (long long)NH_ * HW_ * K_, (long long)HW_ * K_,
        (long long)K_ * HID_, HD_,
        (long long)HW_ * HID_, HD_, NH_, 1.f);
    // out2p = ao2 @ wo2^T + bo2    (32768 x 1024 x 1024) -> reuses v1 buffer
    gemm_kernel<true><<<dim3(8, 256, 1), 256>>>(ao2, wo2, bo2, out2p,
        32768, 1024, 1024, 1024, 1024, 1024, 0, 0, 0, 0, 0, 0, 1, 1.f);
    // out = LN(hidden + out2p)
    add_ln_kernel<4><<<32768, 256>>>(hidden, out2p, g_h, b_h, out, 1024);
}

// round 2
// speedup vs baseline: 3.1900x; 3.1900x over previous
#include <cuda_runtime.h>
#include <math.h>
#include <stdint.h>

#define B_    8
#define HW_   4096
#define K_    256
#define HID_  1024
#define AUX_  512
#define QK_   512
#define NH_   8
#define HD_   128
#define SCALE_ 0.08838834764831845f   // 1/sqrt(128)

// ---------------- scratch (static device global; no runtime allocs) ----------
__device__ float g_scratch[108003328];

// ---------------- helpers -----------------------------------------------------
__device__ __forceinline__ uint32_t f2tf32(float f) {
    uint32_t u;
    asm("cvt.rna.tf32.f32 %0, %1;" : "=r"(u) : "f"(f));
    return u;
}

__device__ __forceinline__ void mma8(float* c, const uint32_t* a, const uint32_t* b) {
    asm volatile(
        "mma.sync.aligned.m16n8k8.row.col.f32.tf32.tf32.f32 "
        "{%0,%1,%2,%3}, {%4,%5,%6,%7}, {%8,%9}, {%0,%1,%2,%3};"
        : "+f"(c[0]), "+f"(c[1]), "+f"(c[2]), "+f"(c[3])
        : "r"(a[0]), "r"(a[1]), "r"(a[2]), "r"(a[3]), "r"(b[0]), "r"(b[1]));
}

__device__ __forceinline__ void cp16(void* s, const void* g) {
    uint32_t sa = (uint32_t)__cvta_generic_to_shared(s);
    asm volatile("cp.async.cg.shared.global [%0], [%1], 16;" :: "r"(sa), "l"(g));
}

// ---------------- tf32 tensor-core batched GEMM ------------------------------
// C[M,N] = alpha * A[M,Kd] * op(B) + bias
// TRANSB: B is [N,Kd] (op = B^T);  else B is [Kd,N].
// Block tile 128x128, BK=16, 8 warps (2m x 4n), warp tile 64x32.
// Kd must be a multiple of 16; M,N multiples of 128.
template<bool TRANSB>
__global__ __launch_bounds__(256) void mma_gemm(
    const float* __restrict__ A, const float* __restrict__ Bm,
    const float* __restrict__ bias, float* __restrict__ C,
    int M, int N, int Kd, int lda, int ldb, int ldc,
    long long sAb, long long sAh, long long sBb, long long sBh,
    long long sCb, long long sCh, int nh, float alpha)
{
    constexpr int LDA_S = 20;                         // [m][k] pad
    constexpr int BSELEM = TRANSB ? 128 * 20 : 16 * 136;
    __shared__ __align__(16) float As[2][128 * LDA_S];
    __shared__ __align__(16) float Bs[2][BSELEM];

    const int z  = blockIdx.z;
    const int bb = z / nh, hh = z - bb * nh;
    A  += bb * sAb + hh * sAh;
    Bm += bb * sBb + hh * sBh;
    C  += bb * sCb + hh * sCh;

    const int m0   = blockIdx.y * 128;
    const int n0   = blockIdx.x * 128;
    const int t    = threadIdx.x;
    const int lane = t & 31;
    const int warp = t >> 5;
    const int wm   = (warp >> 2) * 64;   // 2 warps in m
    const int wn   = (warp & 3) * 32;    // 4 warps in n
    const int gid  = lane >> 2;          // groupID 0..7
    const int tig  = lane & 3;           // thread-in-group 0..3

    float acc[4][4][4];
#pragma unroll
    for (int i = 0; i < 4; i++)
#pragma unroll
        for (int j = 0; j < 4; j++)
#pragma unroll
            for (int r = 0; r < 4; r++) acc[i][j][r] = 0.f;

    auto loadA = [&](int s, int k0) {
#pragma unroll
        for (int i = 0; i < 2; i++) {
            int c   = t + i * 256;          // 512 chunks of 16B
            int row = c >> 2;
            int off = (c & 3) * 4;
            cp16(&As[s][row * LDA_S + off], A + (size_t)(m0 + row) * lda + k0 + off);
        }
    };
    auto loadB = [&](int s, int k0) {
        if (TRANSB) {
#pragma unroll
            for (int i = 0; i < 2; i++) {
                int c   = t + i * 256;
                int row = c >> 2;
                int off = (c & 3) * 4;
                cp16(&Bs[s][row * LDA_S + off], Bm + (size_t)(n0 + row) * ldb + k0 + off);
            }
        } else {
#pragma unroll
            for (int i = 0; i < 2; i++) {
                int c   = t + i * 256;      // 16 rows x 128 cols = 512 chunks
                int row = c >> 5;
                int off = (c & 31) * 4;
                cp16(&Bs[s][row * 136 + off], Bm + (size_t)(k0 + row) * ldb + n0 + off);
            }
        }
    };

    const int nchunk = Kd >> 4;
    loadA(0, 0); loadB(0, 0);
    asm volatile("cp.async.commit_group;");
    if (nchunk > 1) { loadA(1, 16); loadB(1, 16); }
    asm volatile("cp.async.commit_group;");
    asm volatile("cp.async.wait_group 1;");
    __syncthreads();

    for (int ck = 0; ck < nchunk; ck++) {
        const int s = ck & 1;
#pragma unroll
        for (int k8 = 0; k8 < 16; k8 += 8) {
            uint32_t af[4][4], bf[4][2];
            const int kk = k8 + tig;
#pragma unroll
            for (int mt = 0; mt < 4; mt++) {
                const int r = wm + mt * 16 + gid;
                af[mt][0] = f2tf32(As[s][r * LDA_S + kk]);
                af[mt][1] = f2tf32(As[s][(r + 8) * LDA_S + kk]);
                af[mt][2] = f2tf32(As[s][r * LDA_S + kk + 4]);
                af[mt][3] = f2tf32(As[s][(r + 8) * LDA_S + kk + 4]);
            }
#pragma unroll
            for (int nt = 0; nt < 4; nt++) {
                const int col = wn + nt * 8 + gid;
                if (TRANSB) {
                    bf[nt][0] = f2tf32(Bs[s][col * LDA_S + kk]);
                    bf[nt][1] = f2tf32(Bs[s][col * LDA_S + kk + 4]);
                } else {
                    bf[nt][0] = f2tf32(Bs[s][kk * 136 + col]);
                    bf[nt][1] = f2tf32(Bs[s][(kk + 4) * 136 + col]);
                }
            }
#pragma unroll
            for (int mt = 0; mt < 4; mt++)
#pragma unroll
                for (int nt = 0; nt < 4; nt++)
                    mma8(acc[mt][nt], af[mt], bf[nt]);
        }
        __syncthreads();
        if (ck + 2 < nchunk) { loadA(s, (ck + 2) << 4); loadB(s, (ck + 2) << 4); }
        asm volatile("cp.async.commit_group;");
        asm volatile("cp.async.wait_group 1;");
        __syncthreads();
    }

#pragma unroll
    for (int mt = 0; mt < 4; mt++) {
        const int row = m0 + wm + mt * 16 + gid;
#pragma unroll
        for (int nt = 0; nt < 4; nt++) {
            const int col = n0 + wn + nt * 8 + tig * 2;
            float b0v = 0.f, b1v = 0.f;
            if (bias) { b0v = bias[col]; b1v = bias[col + 1]; }
            float2 v;
            v.x = acc[mt][nt][0] * alpha + b0v;
            v.y = acc[mt][nt][1] * alpha + b1v;
            *reinterpret_cast<float2*>(C + (size_t)row * ldc + col) = v;
            v.x = acc[mt][nt][2] * alpha + b0v;
            v.y = acc[mt][nt][3] * alpha + b1v;
            *reinterpret_cast<float2*>(C + (size_t)(row + 8) * ldc + col) = v;
        }
    }
}

// ---------------- softmax, L = 4096, one block per row ----------------------
__global__ __launch_bounds__(256) void softmax4096_kernel(float* __restrict__ X)
{
    float* x = X + (size_t)blockIdx.x * 4096;
    const int t = threadIdx.x;
    float v[16];
    float m = -1e30f;
#pragma unroll
    for (int i = 0; i < 16; i++) { v[i] = x[t + i * 256]; m = fmaxf(m, v[i]); }
    __shared__ float red[8];
    const int lane = t & 31, w = t >> 5;
#pragma unroll
    for (int o = 16; o > 0; o >>= 1) m = fmaxf(m, __shfl_xor_sync(0xffffffffu, m, o));
    if (lane == 0) red[w] = m;
    __syncthreads();
    float bm = red[0];
#pragma unroll
    for (int i = 1; i < 8; i++) bm = fmaxf(bm, red[i]);
    float s = 0.f;
#pragma unroll
    for (int i = 0; i < 16; i++) { v[i] = __expf(v[i] - bm); s += v[i]; }
#pragma unroll
    for (int o = 16; o > 0; o >>= 1) s += __shfl_xor_sync(0xffffffffu, s, o);
    __syncthreads();
    if (lane == 0) red[w] = s;
    __syncthreads();
    float bs = 0.f;
#pragma unroll
    for (int i = 0; i < 8; i++) bs += red[i];
    const float inv = 1.0f / bs;
#pragma unroll
    for (int i = 0; i < 16; i++) x[t + i * 256] = v[i] * inv;
}

// ---------------- softmax, L = 256, one warp per row ------------------------
__global__ __launch_bounds__(256) void softmax256_kernel(float* __restrict__ X)
{
    const int lane = threadIdx.x & 31;
    const int w    = threadIdx.x >> 5;
    float* x = X + ((size_t)blockIdx.x * 8 + w) * 256;
    float v[8];
    float m = -1e30f;
#pragma unroll
    for (int i = 0; i < 8; i++) { v[i] = x[lane + i * 32]; m = fmaxf(m, v[i]); }
#pragma unroll
    for (int o = 16; o > 0; o >>= 1) m = fmaxf(m, __shfl_xor_sync(0xffffffffu, m, o));
    float s = 0.f;
#pragma unroll
    for (int i = 0; i < 8; i++) { v[i] = __expf(v[i] - m); s += v[i]; }
#pragma unroll
    for (int o = 16; o > 0; o >>= 1) s += __shfl_xor_sync(0xffffffffu, s, o);
    const float inv = 1.0f / s;
#pragma unroll
    for (int i = 0; i < 8; i++) x[lane + i * 32] = v[i] * inv;
}

// ---------------- residual add + LayerNorm ----------------------------------
template<int VPT>
__global__ __launch_bounds__(256) void add_ln_kernel(
    const float* __restrict__ R, const float* __restrict__ X,
    const float* __restrict__ g, const float* __restrict__ bta,
    float* __restrict__ Y, int D)
{
    const size_t row = blockIdx.x;
    const float* r = R + row * D;
    const float* x = X + row * D;
    float* y = Y + row * D;
    const int t = threadIdx.x;
    float v[VPT];
    float s = 0.f, sq = 0.f;
#pragma unroll
    for (int i = 0; i < VPT; i++) {
        const int c = t + i * 256;
        v[i] = r[c] + x[c];
        s += v[i]; sq += v[i] * v[i];
    }
    const int lane = t & 31, w = t >> 5;
#pragma unroll
    for (int o = 16; o > 0; o >>= 1) {
        s  += __shfl_xor_sync(0xffffffffu, s, o);
        sq += __shfl_xor_sync(0xffffffffu, sq, o);
    }
    __shared__ float rs[8], rq[8];
    if (lane == 0) { rs[w] = s; rq[w] = sq; }
    __syncthreads();
    s = 0.f; sq = 0.f;
#pragma unroll
    for (int i = 0; i < 8; i++) { s += rs[i]; sq += rq[i]; }
    const float mean = s / D;
    const float var  = sq / D - mean * mean;
    const float inv  = rsqrtf(var + 1e-5f);
#pragma unroll
    for (int i = 0; i < VPT; i++) {
        const int c = t + i * 256;
        y[c] = (v[i] - mean) * inv * g[c] + bta[c];
    }
}

// ---------------- launch ------------------------------------------------------
extern "C" void kernel_launch(void* const* d_in, const int* in_sizes, int n_in,
                              void* d_out, int out_size)
{
    const float* hidden = (const float*)d_in[0];
    const float* aux    = (const float*)d_in[1];
    const float* wq1 = (const float*)d_in[2];  const float* bq1 = (const float*)d_in[3];
    const float* wk1 = (const float*)d_in[4];  const float* bk1 = (const float*)d_in[5];
    const float* wv1 = (const float*)d_in[6];  const float* bv1 = (const float*)d_in[7];
    const float* wo1 = (const float*)d_in[8];  const float* bo1 = (const float*)d_in[9];
    const float* wq2 = (const float*)d_in[10]; const float* bq2 = (const float*)d_in[11];
    const float* wk2 = (const float*)d_in[12]; const float* bk2 = (const float*)d_in[13];
    const float* wv2 = (const float*)d_in[14]; const float* bv2 = (const float*)d_in[15];
    const float* wo2 = (const float*)d_in[16]; const float* bo2 = (const float*)d_in[17];
    const float* g_aux = (const float*)d_in[18]; const float* b_aux = (const float*)d_in[19];
    const float* g_h   = (const float*)d_in[20]; const float* b_h   = (const float*)d_in[21];

    float* scratch = nullptr;
    cudaGetSymbolAddress((void**)&scratch, g_scratch);
    float* q1    = scratch + 0;
    float* k1    = scratch + 1048576;
    float* v1    = scratch + 17825792;
    float* q2    = scratch + 51380224;
    float* k2    = scratch + 68157440;
    float* v2    = scratch + 69206016;
    float* ao1   = scratch + 71303168;
    float* out1  = scratch + 73400320;
    float* ao2   = scratch + 74448896;
    float* out2p = v1;  // v1 dead after attn1@v1; reuse for out2 projection

    float* out     = (float*)d_out;
    float* aux_out = out + (size_t)B_ * HW_ * HID_;
    float* attn2   = aux_out + (size_t)B_ * K_ * AUX_;
    float* attn1   = attn2 + (size_t)B_ * NH_ * HW_ * K_;

    // --- projections from inputs ---
    mma_gemm<true><<<dim3(4, 16, 1), 256>>>(aux, wq1, bq1, q1,
        2048, 512, 512, 512, 512, 512, 0, 0, 0, 0, 0, 0, 1, 1.f);
    mma_gemm<true><<<dim3(4, 256, 1), 256>>>(hidden, wk1, bk1, k1,
        32768, 512, 1024, 1024, 1024, 512, 0, 0, 0, 0, 0, 0, 1, 1.f);
    mma_gemm<true><<<dim3(8, 256, 1), 256>>>(hidden, wv1, bv1, v1,
        32768, 1024, 1024, 1024, 1024, 1024, 0, 0, 0, 0, 0, 0, 1, 1.f);
    mma_gemm<true><<<dim3(4, 256, 1), 256>>>(hidden, wq2, bq2, q2,
        32768, 512, 1024, 1024, 1024, 512, 0, 0, 0, 0, 0, 0, 1, 1.f);

    // --- pack attention: scores (b,h): 256 x 4096, headdim 64 ---
    mma_gemm<true><<<dim3(32, 2, 64), 256>>>(q1, k1, nullptr, attn1,
        256, 4096, 64, 512, 512, 4096,
        (long long)K_ * QK_, 64,
        (long long)HW_ * QK_, 64,
        (long long)NH_ * K_ * HW_, (long long)K_ * HW_, NH_, SCALE_);
    softmax4096_kernel<<<16384, 256>>>(attn1);
    // ao1 = attn1 @ v1 (per head): 256 x 128 x 4096
    mma_gemm<false><<<dim3(1, 2, 64), 256>>>(attn1, v1, nullptr, ao1,
        256, 128, 4096, 4096, 1024, 1024,
        (long long)NH_ * K_ * HW_, (long long)K_ * HW_,
        (long long)HW_ * HID_, HD_,
        (long long)K_ * HID_, HD_, NH_, 1.f);
    // out1 = ao1 @ wo1^T + bo1
    mma_gemm<true><<<dim3(4, 16, 1), 256>>>(ao1, wo1, bo1, out1,
        2048, 512, 1024, 1024, 1024, 512, 0, 0, 0, 0, 0, 0, 1, 1.f);
    add_ln_kernel<2><<<2048, 256>>>(aux, out1, g_aux, b_aux, aux_out, 512);

    // --- unpack attention: k2/v2 from pre-norm out1 ---
    mma_gemm<true><<<dim3(4, 16, 1), 256>>>(out1, wk2, bk2, k2,
        2048, 512, 512, 512, 512, 512, 0, 0, 0, 0, 0, 0, 1, 1.f);
    mma_gemm<true><<<dim3(8, 16, 1), 256>>>(out1, wv2, bv2, v2,
        2048, 1024, 512, 512, 512, 1024, 0, 0, 0, 0, 0, 0, 1, 1.f);
    // scores (b,h): 4096 x 256, headdim 64
    mma_gemm<true><<<dim3(2, 32, 64), 256>>>(q2, k2, nullptr, attn2,
        4096, 256, 64, 512, 512, 256,
        (long long)HW_ * QK_, 64,
        (long long)K_ * QK_, 64,
        (long long)NH_ * HW_ * K_, (long long)HW_ * K_, NH_, SCALE_);
    softmax256_kernel<<<32768, 256>>>(attn2);
    // ao2 = attn2 @ v2 (per head): 4096 x 128 x 256
    mma_gemm<false><<<dim3(1, 32, 64), 256>>>(attn2, v2, nullptr, ao2,
        4096, 128, 256, 256, 1024, 1024,
        (long long)NH_ * HW_ * K_, (long long)HW_ * K_,
        (long long)K_ * HID_, HD_,
        (long long)HW_ * HID_, HD_, NH_, 1.f);
    // out2p = ao2 @ wo2^T + bo2 (reuses v1 buffer)
    mma_gemm<true><<<dim3(8, 256, 1), 256>>>(ao2, wo2, bo2, out2p,
        32768, 1024, 1024, 1024, 1024, 1024, 0, 0, 0, 0, 0, 0, 1, 1.f);
    add_ln_kernel<4><<<32768, 256>>>(hidden, out2p, g_h, b_h, out, 1024);
}